// round 3
// baseline (speedup 1.0000x reference)
#include <cuda_runtime.h>
#include <cstdint>
#include <cstddef>

#define BB   32
#define SS   1024
#define HH   256
#define G4   1024          // 4*H
#define NBLK_DIR 64        // blocks per direction in recurrent kernel
#define HP2  264           // padded row stride (floats): conflict-free + 16B aligned

#define HN_OFF (32ull*1024ull*512ull)            // 16777216
#define CN_OFF (HN_OFF + 2ull*32ull*512ull)      // +32768

// ---------------- device scratch (no cudaMalloc allowed) ----------------
__device__ float g_xproj[2][SS*BB][G4];   // [dir][s*32+b][gate]  268MB
__device__ float g_out0[SS*BB][512];      // layer0 output [s*32+b][ch]
__device__ float g_h[2][BB][HH];          // per-dir hidden state
__device__ unsigned g_cnt[2][2][SS];      // [layer][dir][step] barrier counters

// ---------------- helpers ------------------------------------------------
__device__ __forceinline__ void fma2(unsigned long long &d,
                                     unsigned long long a,
                                     unsigned long long b) {
    asm("fma.rn.f32x2 %0, %1, %2, %0;" : "+l"(d) : "l"(a), "l"(b));
}
__device__ __forceinline__ float hsum2(unsigned long long v) {
    return __uint_as_float((unsigned)v) + __uint_as_float((unsigned)(v >> 32));
}
__device__ __forceinline__ float sigf(float x) { return 1.f / (1.f + expf(-x)); }

// ---------------- reset barrier counters (runs each replay) -------------
__global__ void reset_kernel() {
    int i = blockIdx.x * blockDim.x + threadIdx.x;
    if (i < 2 * 2 * SS) ((unsigned*)g_cnt)[i] = 0u;
}

// ---------------- input projection GEMM (f32x2 packed) -------------------
// out[dir][m][g] = sum_k X(m,k) * W_dir[g][k] + bih[g] + bhh[g]
// BM=128, BN=64, BK=16, 256 threads, 8x4 per thread, acc packed over k-pairs.
#define ASTR 20
__global__ void __launch_bounds__(256) xproj_kernel(
    const float* __restrict__ xin, int layer, int K,
    const float* __restrict__ Wf, const float* __restrict__ Wb,
    const float* __restrict__ bihf, const float* __restrict__ bhhf,
    const float* __restrict__ bihb, const float* __restrict__ bhhb)
{
    __shared__ float As[128][ASTR];
    __shared__ float Bs[64][ASTR];
    const int dir = blockIdx.z;
    const float* W  = dir ? Wb   : Wf;
    const float* bi = dir ? bihb : bihf;
    const float* bh = dir ? bhhb : bhhf;
    const float* X  = (layer == 0) ? xin : &g_out0[0][0];
    const int m0 = blockIdx.y * 128;
    const int n0 = blockIdx.x * 64;
    const int tid = threadIdx.x;
    const int ty = tid >> 4, tx = tid & 15;

    unsigned long long acc[8][4];
    #pragma unroll
    for (int i = 0; i < 8; i++)
        #pragma unroll
        for (int j = 0; j < 4; j++) acc[i][j] = 0ull;

    for (int k0 = 0; k0 < K; k0 += 16) {
        // stage A tile (128 rows x 16 k), m-major
        #pragma unroll
        for (int jj = 0; jj < 2; jj++) {
            int idx = tid * 2 + jj;
            int row = idx >> 2;
            int kk  = (idx & 3) << 2;
            int m = m0 + row;
            const float* ap;
            if (layer == 0) {
                int s = m >> 5, b = m & 31;
                ap = X + ((size_t)b * SS + s) * 256 + k0 + kk;
            } else {
                ap = X + (size_t)m * 512 + k0 + kk;
            }
            *(float4*)&As[row][kk] = *(const float4*)ap;
        }
        // stage B tile (64 gate-rows x 16 k), n-major
        {
            int n = tid >> 2, kk = (tid & 3) << 2;
            *(float4*)&Bs[n][kk] = *(const float4*)(W + (size_t)(n0 + n) * K + k0 + kk);
        }
        __syncthreads();
        #pragma unroll
        for (int kp = 0; kp < 8; kp++) {
            unsigned long long b2[4];
            #pragma unroll
            for (int j = 0; j < 4; j++)
                b2[j] = *(const unsigned long long*)&Bs[tx * 4 + j][kp * 2];
            #pragma unroll
            for (int i = 0; i < 8; i++) {
                unsigned long long a2 = *(const unsigned long long*)&As[ty * 8 + i][kp * 2];
                #pragma unroll
                for (int j = 0; j < 4; j++) fma2(acc[i][j], a2, b2[j]);
            }
        }
        __syncthreads();
    }
    float bs[4];
    #pragma unroll
    for (int j = 0; j < 4; j++) {
        int c = n0 + tx * 4 + j;
        bs[j] = bi[c] + bh[c];
    }
    #pragma unroll
    for (int i = 0; i < 8; i++) {
        int m = m0 + ty * 8 + i;
        float4 o;
        o.x = hsum2(acc[i][0]) + bs[0]; o.y = hsum2(acc[i][1]) + bs[1];
        o.z = hsum2(acc[i][2]) + bs[2]; o.w = hsum2(acc[i][3]) + bs[3];
        *(float4*)&g_xproj[dir][m][n0 + tx * 4] = o;
    }
}

// ---------------- persistent recurrent kernel ----------------------------
// 128 blocks x 256 threads; dir = bx&1, block owns 4 h-indices (16 gate rows).
// thread = (kh, bg, r): k-half x 4-batch-group x row. f32x2 packed dots.
// One release/acquire global barrier per step per direction, with backoff.
__global__ void __launch_bounds__(256, 1) recurrent_kernel(
    int layer,
    const float* __restrict__ Whf, const float* __restrict__ Whb,
    const float* __restrict__ mask, float* __restrict__ dout)
{
    extern __shared__ float smem[];
    float (*w_sh)[HP2] = (float(*)[HP2])smem;                 // 16 x 264
    float (*h_sh)[HP2] = (float(*)[HP2])(smem + 16 * HP2);    // 32 x 264
    float* part        = smem + 48 * HP2;                     // [2][32][16]

    const int bx  = blockIdx.x;
    const int dir = bx & 1;
    const int j0  = (bx >> 1) * 4;       // 0..252
    const int tid = threadIdx.x;
    const float* Whh = dir ? Whb : Whf;

    // persistent weight load: 16 gate rows (r = gate*4+jj)
    for (int i = tid; i < 16 * 64; i += 256) {
        int r  = i >> 6;
        int kk = (i & 63) << 2;
        int grow = (r >> 2) * 256 + j0 + (r & 3);
        *(float4*)&w_sh[r][kk] = *(const float4*)&Whh[(size_t)grow * 256 + kk];
    }

    const int r  = tid & 15;
    const int bg = (tid >> 4) & 7;
    const int kh = tid >> 7;
    const int kbase = kh * 128;

    // update role (tid < 128): owns (batch ub, h-index j0+uj)
    const int ub = tid >> 2, uj = tid & 3;
    float c_reg = 0.f;

    // prefetch step-0 xproj contribution + mask
    float xp[4]; float mt = 0.f;
    {
        const int s0 = dir ? (SS - 1) : 0;
        if (tid < 128) {
            const float* xb = &g_xproj[dir][(size_t)(s0 * 32 + ub)][j0 + uj];
            #pragma unroll
            for (int g = 0; g < 4; g++) xp[g] = __ldcs(xb + g * 256);
            mt = mask[ub * SS + s0];
        }
    }
    __syncthreads();

    for (int t = 0; t < SS; t++) {
        const int s = dir ? (SS - 1 - t) : t;

        // stage previous h into shared (L2-coherent loads)
        if (t == 0) {
            for (int i = tid; i < 2048; i += 256) {
                int row = i >> 6, kk = (i & 63) << 2;
                *(float4*)&h_sh[row][kk] = make_float4(0.f, 0.f, 0.f, 0.f);
            }
        } else {
            const float4* src = (const float4*)&g_h[dir][0][0];
            for (int i = tid; i < 2048; i += 256) {
                int row = i >> 6, kk = (i & 63) << 2;
                *(float4*)&h_sh[row][kk] = __ldcg(src + i);
            }
        }
        __syncthreads();

        // packed dot: thread covers row r, batches 4bg..4bg+3, k-half kh
        unsigned long long aLo[4] = {0ull,0ull,0ull,0ull};
        unsigned long long aHi[4] = {0ull,0ull,0ull,0ull};
        #pragma unroll
        for (int it = 0; it < 32; it++) {
            int kk = kbase + it * 4;
            ulonglong2 w2 = *(const ulonglong2*)&w_sh[r][kk];
            #pragma unroll
            for (int j = 0; j < 4; j++) {
                ulonglong2 h2 = *(const ulonglong2*)&h_sh[bg * 4 + j][kk];
                fma2(aLo[j], h2.x, w2.x);
                fma2(aHi[j], h2.y, w2.y);
            }
        }
        #pragma unroll
        for (int j = 0; j < 4; j++)
            part[(kh * 32 + bg * 4 + j) * 16 + r] = hsum2(aLo[j]) + hsum2(aHi[j]);
        __syncthreads();

        // gate nonlinearities + state update (block owns j0..j0+3)
        if (tid < 128) {
            float gv[4];
            #pragma unroll
            for (int g = 0; g < 4; g++) {
                int rr = g * 4 + uj;
                gv[g] = part[(0 * 32 + ub) * 16 + rr]
                      + part[(1 * 32 + ub) * 16 + rr] + xp[g];
            }
            float iv = sigf(gv[0]);
            float fv = sigf(gv[1]);
            float gg = tanhf(gv[2]);
            float ov = sigf(gv[3]);
            float c = fv * c_reg + iv * gg;
            c *= mt;                              // c0 = 0
            float h = ov * tanhf(c) * mt;         // h0 = 0
            c_reg = c;
            __stcg(&g_h[dir][ub][j0 + uj], h);
            if (layer == 0)
                g_out0[s * 32 + ub][dir * 256 + j0 + uj] = h;
            else
                dout[((size_t)ub * SS + s) * 512 + dir * 256 + j0 + uj] = h;
            if (t == SS - 1) {
                size_t off = (size_t)layer * BB * 512 + (size_t)ub * 512 + dir * 256 + j0 + uj;
                dout[HN_OFF + off] = h;
                dout[CN_OFF + off] = c;
            }
        }

        // prefetch next step's xproj contribution + mask (hides DRAM latency)
        if (t + 1 < SS && tid < 128) {
            const int sn = dir ? (SS - 2 - t) : (t + 1);
            const float* xb = &g_xproj[dir][(size_t)(sn * 32 + ub)][j0 + uj];
            #pragma unroll
            for (int g = 0; g < 4; g++) xp[g] = __ldcs(xb + g * 256);
            mt = mask[ub * SS + sn];
        }

        // inter-block barrier: release-add, then polite relaxed poll with
        // nanosleep backoff, one acquire load to establish ordering.
        if (t < SS - 1) {
            __syncthreads();
            if (tid == 0) {
                unsigned* cp = &g_cnt[layer][dir][t];
                asm volatile("red.release.gpu.global.add.u32 [%0], 1;"
                             :: "l"(cp) : "memory");
                unsigned v;
                asm volatile("ld.relaxed.gpu.global.u32 %0, [%1];"
                             : "=r"(v) : "l"(cp) : "memory");
                unsigned ns = 32;
                while (v < NBLK_DIR) {
                    __nanosleep(ns);
                    if (ns < 256) ns <<= 1;
                    asm volatile("ld.relaxed.gpu.global.u32 %0, [%1];"
                                 : "=r"(v) : "l"(cp) : "memory");
                }
                asm volatile("ld.acquire.gpu.global.u32 %0, [%1];"
                             : "=r"(v) : "l"(cp) : "memory");
            }
            __syncthreads();
        }
    }
}

// ---------------- launch ------------------------------------------------
extern "C" void kernel_launch(void* const* d_in, const int* in_sizes, int n_in,
                              void* d_out, int out_size)
{
    const float* inputs  = (const float*)d_in[0];
    const float* mask    = (const float*)d_in[1];
    const float* l0f_Wih = (const float*)d_in[2];
    const float* l0f_Whh = (const float*)d_in[3];
    const float* l0f_bih = (const float*)d_in[4];
    const float* l0f_bhh = (const float*)d_in[5];
    const float* l0b_Wih = (const float*)d_in[6];
    const float* l0b_Whh = (const float*)d_in[7];
    const float* l0b_bih = (const float*)d_in[8];
    const float* l0b_bhh = (const float*)d_in[9];
    const float* l1f_Wih = (const float*)d_in[10];
    const float* l1f_Whh = (const float*)d_in[11];
    const float* l1f_bih = (const float*)d_in[12];
    const float* l1f_bhh = (const float*)d_in[13];
    const float* l1b_Wih = (const float*)d_in[14];
    const float* l1b_Whh = (const float*)d_in[15];
    const float* l1b_bih = (const float*)d_in[16];
    const float* l1b_bhh = (const float*)d_in[17];
    float* out = (float*)d_out;

    const int shmem = (48 * HP2 + 2 * 32 * 16) * 4;   // 54784 bytes
    cudaFuncSetAttribute(recurrent_kernel,
                         cudaFuncAttributeMaxDynamicSharedMemorySize, shmem);

    reset_kernel<<<16, 256>>>();

    dim3 g(16, 256, 2);   // N/64, M/128, dirs
    xproj_kernel<<<g, 256>>>(inputs, 0, 256,
                             l0f_Wih, l0b_Wih, l0f_bih, l0f_bhh, l0b_bih, l0b_bhh);
    recurrent_kernel<<<128, 256, shmem>>>(0, l0f_Whh, l0b_Whh, mask, out);

    xproj_kernel<<<g, 256>>>(nullptr, 1, 512,
                             l1f_Wih, l1b_Wih, l1f_bih, l1f_bhh, l1b_bih, l1b_bhh);
    recurrent_kernel<<<128, 256, shmem>>>(1, l1f_Whh, l1b_Whh, mask, out);
}

// round 5
// speedup vs baseline: 1.3363x; 1.3363x over previous
#include <cuda_runtime.h>
#include <cstdint>
#include <cstddef>

#define BB   32
#define SS   1024
#define HH   256
#define G4   1024          // 4*H

#define WST  260           // w_sh row stride (floats): conflict-free, 16B-aligned
#define HST  260           // h_sh row stride

#define HN_OFF (32ull*1024ull*512ull)            // 16777216
#define CN_OFF (HN_OFF + 2ull*32ull*512ull)      // +32768

// ---------------- device scratch (no cudaMalloc allowed) ----------------
__device__ float g_xproj[2][SS*BB][G4];   // [dir][s*32+b][gate]  268MB
__device__ float g_out0[SS*BB][512];      // layer0 output [s*32+b][ch]

// ---------------- helpers ------------------------------------------------
__device__ __forceinline__ void fma2(unsigned long long &d,
                                     unsigned long long a,
                                     unsigned long long b) {
    asm("fma.rn.f32x2 %0, %1, %2, %0;" : "+l"(d) : "l"(a), "l"(b));
}
__device__ __forceinline__ float hsum2(unsigned long long v) {
    return __uint_as_float((unsigned)v) + __uint_as_float((unsigned)(v >> 32));
}
__device__ __forceinline__ float sigf(float x) { return 1.f / (1.f + expf(-x)); }

__device__ __forceinline__ uint32_t smem_u32(const void* p) {
    return (uint32_t)__cvta_generic_to_shared(p);
}
__device__ __forceinline__ void st_cluster_f32(uint32_t laddr, uint32_t rk, float v) {
    uint32_t ra;
    asm volatile("mapa.shared::cluster.u32 %0, %1, %2;"
                 : "=r"(ra) : "r"(laddr), "r"(rk));
    asm volatile("st.shared::cluster.f32 [%0], %1;"
                 :: "r"(ra), "f"(v) : "memory");
}

// ---------------- input projection GEMM (R0-proven scalar) ---------------
// out[dir][m][g] = sum_k X(m,k) * W_dir[g][k] + bih[g] + bhh[g]
// BM=128, BN=64, BK=16, 256 threads, 8x4 per thread.
__global__ void __launch_bounds__(256) xproj_kernel(
    const float* __restrict__ xin, int layer, int K,
    const float* __restrict__ Wf, const float* __restrict__ Wb,
    const float* __restrict__ bihf, const float* __restrict__ bhhf,
    const float* __restrict__ bihb, const float* __restrict__ bhhb)
{
    __shared__ float As[16][128];
    __shared__ float Bs[16][64];
    const int dir = blockIdx.z;
    const float* W  = dir ? Wb   : Wf;
    const float* bi = dir ? bihb : bihf;
    const float* bh = dir ? bhhb : bhhf;
    const float* X  = (layer == 0) ? xin : &g_out0[0][0];
    const int m0 = blockIdx.y * 128;
    const int n0 = blockIdx.x * 64;
    const int tid = threadIdx.x;
    const int ty = tid >> 4, tx = tid & 15;

    float acc[8][4];
    #pragma unroll
    for (int i = 0; i < 8; i++)
        #pragma unroll
        for (int j = 0; j < 4; j++) acc[i][j] = 0.f;

    for (int k0 = 0; k0 < K; k0 += 16) {
        #pragma unroll
        for (int jj = 0; jj < 2; jj++) {
            int idx = tid * 2 + jj;
            int row = idx >> 2;
            int kk  = (idx & 3) << 2;
            int m = m0 + row;
            const float* ap;
            if (layer == 0) {
                int s = m >> 5, b = m & 31;
                ap = X + ((size_t)b * SS + s) * 256 + k0 + kk;
            } else {
                ap = X + (size_t)m * 512 + k0 + kk;
            }
            float4 v = *(const float4*)ap;
            As[kk + 0][row] = v.x; As[kk + 1][row] = v.y;
            As[kk + 2][row] = v.z; As[kk + 3][row] = v.w;
        }
        {
            int n = tid >> 2, kk = (tid & 3) << 2;
            float4 v = *(const float4*)(W + (size_t)(n0 + n) * K + k0 + kk);
            Bs[kk + 0][n] = v.x; Bs[kk + 1][n] = v.y;
            Bs[kk + 2][n] = v.z; Bs[kk + 3][n] = v.w;
        }
        __syncthreads();
        #pragma unroll
        for (int kk = 0; kk < 16; kk++) {
            float4 a0 = *(const float4*)&As[kk][ty * 8];
            float4 a1 = *(const float4*)&As[kk][ty * 8 + 4];
            float4 bv = *(const float4*)&Bs[kk][tx * 4];
            float ar[8] = {a0.x, a0.y, a0.z, a0.w, a1.x, a1.y, a1.z, a1.w};
            float br[4] = {bv.x, bv.y, bv.z, bv.w};
            #pragma unroll
            for (int i = 0; i < 8; i++)
                #pragma unroll
                for (int j = 0; j < 4; j++)
                    acc[i][j] += ar[i] * br[j];
        }
        __syncthreads();
    }
    float bs[4];
    #pragma unroll
    for (int j = 0; j < 4; j++) {
        int c = n0 + tx * 4 + j;
        bs[j] = bi[c] + bh[c];
    }
    #pragma unroll
    for (int i = 0; i < 8; i++) {
        int m = m0 + ty * 8 + i;
        float4 o;
        o.x = acc[i][0] + bs[0]; o.y = acc[i][1] + bs[1];
        o.z = acc[i][2] + bs[2]; o.w = acc[i][3] + bs[3];
        *(float4*)&g_xproj[dir][m][n0 + tx * 4] = o;
    }
}

// ---------------- cluster-parallel recurrent kernel ----------------------
// 16 clusters x 8 CTAs. Cluster = (dir, batch group of 4). Batch chains are
// independent -> only cluster-scope sync needed. CTA rank owns h-indices
// [32r, 32r+32) (all 4 gates): Whh slice (128 rows x 256) persistent in smem.
// Per step: packed-f32x2 dots, block-local gate update, h pushed to all 8
// CTAs' smem via st.shared::cluster, one barrier.cluster.
__global__ void __launch_bounds__(256, 1) __cluster_dims__(8, 1, 1)
rec_kernel(int layer,
           const float* __restrict__ Whf, const float* __restrict__ Whb,
           const float* __restrict__ mask, float* __restrict__ dout)
{
    extern __shared__ float sm[];
    float* w_sh   = sm;              // [128][WST]
    float* h_base = sm + 128 * WST;  // [2][4][HST]
    float* part   = h_base + 8 * HST;// [8][4][4][32]

    const int bx   = blockIdx.x;
    const int cid  = bx >> 3;
    const int rank = bx & 7;
    const int dir  = cid & 1;
    const int bg4  = (cid >> 1) * 4;         // first batch of this cluster
    const int tid  = threadIdx.x;
    const float* Whh = dir ? Whb : Whf;

    // persistent weight load: local row r = g*32+jl -> Whh row g*256+rank*32+jl
    for (int i = tid; i < 128 * 64; i += 256) {
        int r  = i >> 6;
        int kk = (i & 63) << 2;
        int g = r >> 5, jl = r & 31;
        *(float4*)&w_sh[r * WST + kk] =
            *(const float4*)&Whh[((size_t)(g * 256 + rank * 32 + jl)) * 256 + kk];
    }
    // zero h buffer 0
    for (int i = tid; i < 4 * HST; i += 256) h_base[i] = 0.f;

    // compute-role mapping: warp = k-slice (32 k), lane = j-local
    const int kq   = tid >> 5;
    const int lane = tid & 31;
    const int k0   = kq * 32;

    // update-role (tid<128): b = tid>>5 (0..3), jl = tid&31
    const int ub = tid >> 5, ujl = tid & 31;
    const int bglobal = bg4 + ub;
    const int jglob = rank * 32 + ujl;
    float c_reg = 0.f;

    // prefetch step-0 xproj + mask
    float xp[4]; float mt = 0.f;
    if (tid < 128) {
        const int s0 = dir ? (SS - 1) : 0;
        const float* xb = &g_xproj[dir][(size_t)(s0 * 32 + bglobal)][jglob];
        #pragma unroll
        for (int g = 0; g < 4; g++) xp[g] = __ldcs(xb + g * 256);
        mt = mask[bglobal * SS + s0];
    }
    __syncthreads();

    int p = 0;
    for (int t = 0; t < SS; t++) {
        const int s = dir ? (SS - 1 - t) : t;
        const float* hb = h_base + p * 4 * HST;

        // packed dots: acc[g][b] over this warp's 32-k slice
        unsigned long long acc[4][4];
        #pragma unroll
        for (int g = 0; g < 4; g++)
            #pragma unroll
            for (int b = 0; b < 4; b++) acc[g][b] = 0ull;

        #pragma unroll
        for (int it = 0; it < 8; it++) {
            int kk = k0 + it * 4;
            ulonglong2 h2[4];
            #pragma unroll
            for (int b = 0; b < 4; b++)
                h2[b] = *(const ulonglong2*)&hb[b * HST + kk];
            #pragma unroll
            for (int g = 0; g < 4; g++) {
                ulonglong2 w2 = *(const ulonglong2*)&w_sh[(g * 32 + lane) * WST + kk];
                #pragma unroll
                for (int b = 0; b < 4; b++) {
                    fma2(acc[g][b], h2[b].x, w2.x);
                    fma2(acc[g][b], h2[b].y, w2.y);
                }
            }
        }
        #pragma unroll
        for (int g = 0; g < 4; g++)
            #pragma unroll
            for (int b = 0; b < 4; b++)
                part[(((kq * 4 + g) * 4 + b) * 32) + lane] = hsum2(acc[g][b]);
        __syncthreads();

        // gate combine + state update + h push
        if (tid < 128) {
            float gv[4];
            #pragma unroll
            for (int g = 0; g < 4; g++) {
                float sv = xp[g];
                #pragma unroll
                for (int q = 0; q < 8; q++)
                    sv += part[(((q * 4 + g) * 4 + ub) * 32) + ujl];
                gv[g] = sv;
            }
            float iv = sigf(gv[0]);
            float fv = sigf(gv[1]);
            float gg = tanhf(gv[2]);
            float ov = sigf(gv[3]);
            float c = (fv * c_reg + iv * gg) * mt;     // c0 = 0
            float h = ov * tanhf(c) * mt;              // h0 = 0
            c_reg = c;

            // push h into next buffer of all 8 CTAs (incl. self)
            float* hn = h_base + (p ^ 1) * 4 * HST + ub * HST + jglob;
            uint32_t laddr = smem_u32(hn);
            #pragma unroll
            for (int rk = 0; rk < 8; rk++) st_cluster_f32(laddr, rk, h);

            // sequence output
            if (layer == 0)
                g_out0[s * 32 + bglobal][dir * 256 + jglob] = h;
            else
                dout[((size_t)bglobal * SS + s) * 512 + dir * 256 + jglob] = h;
            if (t == SS - 1) {
                size_t off = (size_t)layer * BB * 512 + (size_t)bglobal * 512
                           + dir * 256 + jglob;
                dout[HN_OFF + off] = h;
                dout[CN_OFF + off] = c;
            }

            // prefetch next step's xproj + mask
            if (t + 1 < SS) {
                const int sn = dir ? (SS - 2 - t) : (t + 1);
                const float* xb = &g_xproj[dir][(size_t)(sn * 32 + bglobal)][jglob];
                #pragma unroll
                for (int g = 0; g < 4; g++) xp[g] = __ldcs(xb + g * 256);
                mt = mask[bglobal * SS + sn];
            }
        }

        // cluster barrier: release DSMEM pushes, acquire peers' pushes.
        asm volatile("barrier.cluster.arrive.aligned;" ::: "memory");
        asm volatile("barrier.cluster.wait.aligned;"   ::: "memory");
        p ^= 1;
    }
}

// ---------------- launch ------------------------------------------------
extern "C" void kernel_launch(void* const* d_in, const int* in_sizes, int n_in,
                              void* d_out, int out_size)
{
    const float* inputs  = (const float*)d_in[0];
    const float* mask    = (const float*)d_in[1];
    const float* l0f_Wih = (const float*)d_in[2];
    const float* l0f_Whh = (const float*)d_in[3];
    const float* l0f_bih = (const float*)d_in[4];
    const float* l0f_bhh = (const float*)d_in[5];
    const float* l0b_Wih = (const float*)d_in[6];
    const float* l0b_Whh = (const float*)d_in[7];
    const float* l0b_bih = (const float*)d_in[8];
    const float* l0b_bhh = (const float*)d_in[9];
    const float* l1f_Wih = (const float*)d_in[10];
    const float* l1f_Whh = (const float*)d_in[11];
    const float* l1f_bih = (const float*)d_in[12];
    const float* l1f_bhh = (const float*)d_in[13];
    const float* l1b_Wih = (const float*)d_in[14];
    const float* l1b_Whh = (const float*)d_in[15];
    const float* l1b_bih = (const float*)d_in[16];
    const float* l1b_bhh = (const float*)d_in[17];
    float* out = (float*)d_out;

    // dynamic smem: weights 128*260 + h 2*4*260 + partials 8*4*4*32 floats
    const int shmem = (128 * WST + 8 * HST + 8 * 4 * 4 * 32) * 4;  // 157824 B
    static int once = 0;
    (void)once;
    cudaFuncSetAttribute(rec_kernel,
                         cudaFuncAttributeMaxDynamicSharedMemorySize, shmem);

    dim3 g(16, 256, 2);   // N/64, M/128, dirs
    xproj_kernel<<<g, 256>>>(inputs, 0, 256,
                             l0f_Wih, l0b_Wih, l0f_bih, l0f_bhh, l0b_bih, l0b_bhh);
    rec_kernel<<<128, 256, shmem>>>(0, l0f_Whh, l0b_Whh, mask, out);

    xproj_kernel<<<g, 256>>>(nullptr, 1, 512,
                             l1f_Wih, l1b_Wih, l1f_bih, l1f_bhh, l1b_bih, l1b_bhh);
    rec_kernel<<<128, 256, shmem>>>(1, l1f_Whh, l1b_Whh, mask, out);
}